// round 10
// baseline (speedup 1.0000x reference)
#include <cuda_runtime.h>

#define BN   8
#define CN   64
#define HN   256
#define WN   256
#define HP   257
#define WP   257
#define HWN  (HN * WN)          // 65536
#define NPIX (HP * WP)          // 66049
#define LN_EPS 1e-5f
#define NEG_SLOPE 0.01f

// Padded channel-sum plane: cs(h,w) stored at [(h+3)*CST + (w+4)].
// 262 rows (cs rows -3..258), stride 268 (cols -4..263). Border is zero
// (zero-initialized device globals; interior-only writes). Composed 6x6
// stencil taps (rows/cols -3..+2) never leave the plane.
#define CROWS 262
#define CST   268
#define CPLANE (CROWS * CST)

#define NBLK  74                // blocks per image
#define NGRID (NBLK * BN)       // 592 = 4 * 148 SMs -> single resident wave
#define NTHR  256
#define Q4    (HWN / 4)         // 16384 float4 columns per image plane

// Scratch (static device globals — allowed)
__device__ float g_csp[BN * CPLANE];       // padded channel sum (~2.25 MB)
__device__ float g_part[BN * NBLK * 2];    // per-block (sum, sumsq)
__device__ unsigned int g_tkt[BN * 32];    // per-image ticket counters,
                                           // 128B apart; monotone (each launch
                                           // adds exactly 2*NBLK per image ->
                                           // multiple of NBLK at launch start,
                                           // graph-replay safe)

// ---------------------------------------------------------------------------
// Per-image ticket barrier: only the 74 blocks of one image synchronize.
// Single resident wave (launch_bounds(256,4), 592 blocks) => spin is safe.
// ---------------------------------------------------------------------------
__device__ __forceinline__ void img_barrier(int tid, int b) {
    __syncthreads();
    if (tid == 0) {
        __threadfence();                              // publish this block's stores
        unsigned* c = &g_tkt[b * 32];
        unsigned t = atomicAdd(c, 1u) + 1u;
        unsigned target = ((t + NBLK - 1u) / NBLK) * NBLK;
        volatile unsigned* vc = c;
        while (*vc < target) __nanosleep(64);
    }
    __syncthreads();
    __threadfence();                                  // acquire peers' stores
}

// ---------------------------------------------------------------------------
// One persistent kernel: chansum -> per-image barrier -> 36-tap composed
// stencil (+ LN partials) -> per-image barrier -> stats + norm + LeakyReLU.
// ---------------------------------------------------------------------------
__global__ void __launch_bounds__(NTHR, 4)
k_all(const float* __restrict__ x, const float* __restrict__ cw,
      const float* __restrict__ cb, float* __restrict__ out) {
    __shared__ float s_c6[36];                 // composed 6x6 stencil coeffs
    __shared__ float s_tile[9 * CST];          // 9 padded rows (9.4 KB)
    __shared__ float s_red[8][2];

    const int tid = threadIdx.x;
    const int blk = blockIdx.x;
    const int b   = blk / NBLK;                // this block's image
    const int xb  = blk - b * NBLK;            // index within image [0,74)

    // ---- Phase 0: channel sum for image b, block-proportional columns ----
    {
        unsigned base = ((unsigned)xb * Q4) / NBLK;          // 221-222 cols/blk
        unsigned end  = ((unsigned)(xb + 1) * Q4) / NBLK;
        unsigned col  = base + (unsigned)tid;
        if (col < end) {
            const float4* xp = reinterpret_cast<const float4*>(x)
                               + (size_t)b * CN * Q4 + col;
            float ax = 0.f, ay = 0.f, az = 0.f, aw = 0.f;
#pragma unroll
            for (int cc = 0; cc < CN; cc += 8) {
                float4 buf[8];
#pragma unroll
                for (int i = 0; i < 8; ++i)
                    buf[i] = __ldcs(xp + (size_t)(cc + i) * Q4);
#pragma unroll
                for (int i = 0; i < 8; ++i) {
                    ax += buf[i].x; ay += buf[i].y; az += buf[i].z; aw += buf[i].w;
                }
            }
            int p = (int)col * 4;
            int h = p >> 8, w = p & 255;
            *reinterpret_cast<float4*>(
                g_csp + (size_t)b * CPLANE + (h + 3) * CST + (w + 4)) =
                make_float4(ax, ay, az, aw);
        }
    }

    // ---- Composed coefficients: pool(2) o 16-tap shift stencil = 6x6 ----
    if (tid < 36) {
        const signed char tdr[16] = {2,-2, 2,-2, 2,-2, 2,-2, 2,-2, 1,-1, 0,0, -1,1};
        const signed char tdc[16] = {2,-2, 1,-1, 0, 0,-1, 1,-2, 2,-2, 2,-2,2, -2,2};
        const signed char twi[16] = {0, 0, 1, 1, 2, 2, 3, 3, 4, 4, 5, 5, 6,6,  7,7};
        const signed char tsg[16] = {1,-1, 1,-1, 1,-1, 1,-1, 1,-1, 1,-1, 1,-1, 1,-1};
        int r = tid / 6 - 3, c = tid % 6 - 3;
        float acc = 0.f;
        for (int t2 = 0; t2 < 16; ++t2) {
            int ur = r - tdr[t2], uc = c - tdc[t2];
            if ((ur == 0 || ur == -1) && (uc == 0 || uc == -1))
                acc += (float)tsg[t2] * cw[twi[t2]];
        }
        s_c6[tid] = 0.25f * acc;
    }

    img_barrier(tid, b);                       // image b's cs plane ready

    // ---- Phase B: row-aligned tile, 5 consecutive pixels per thread ----
    // Block covers output rows [r0, r1) of image b (3 or 4 rows).
    const int r0 = (xb * HP) / NBLK;
    const int r1 = ((xb + 1) * HP) / NBLK;
    const int nrows = r1 - r0;
    const float* __restrict__ plane = g_csp + (size_t)b * CPLANE;

    // Tile = padded rows r0 .. r0+8 (covers taps for output rows r0..r0+3;
    // max r0 = 253 -> r0+8 = 261 = last plane row, no bounds check needed).
    for (int i4 = tid; i4 < 9 * (CST / 4); i4 += NTHR) {
        int r  = i4 / (CST / 4);
        int c4 = i4 - r * (CST / 4);
        reinterpret_cast<float4*>(s_tile)[i4] =
            *(reinterpret_cast<const float4*>(plane + (size_t)(r0 + r) * CST) + c4);
    }
    __syncthreads();

    // Thread -> (row ri, columns col0..col0+4). 52 threads per row; the
    // cross-thread column stride of 5 is coprime with 32 banks => all
    // neighborhood LDS are conflict-free.
    const int ri   = tid / 52;
    const int col0 = (tid - ri * 52) * 5;
    const bool act = (tid < 52 * 4) && (ri < nrows);
    const int h    = r0 + ri;
    const int nv   = (HP - col0 < 5) ? (HP - col0) : 5;   // valid pixels (2..5)

    const float bias = __ldg(cb);
    float acc[5];
    float lsum = 0.f, lsq = 0.f;
#pragma unroll
    for (int k = 0; k < 5; ++k) acc[k] = bias;

    if (act) {
        const float* tb = s_tile + (h - r0) * CST + col0 + 1;
#pragma unroll
        for (int rr = 0; rr < 6; ++rr) {
            float t[10];
#pragma unroll
            for (int q = 0; q < 10; ++q) t[q] = tb[rr * CST + q];
#pragma unroll
            for (int c = 0; c < 6; ++c) {
                float cf = s_c6[rr * 6 + c];             // broadcast, no conflict
#pragma unroll
                for (int k = 0; k < 5; ++k)
                    acc[k] = fmaf(cf, t[c + k], acc[k]);
            }
        }
#pragma unroll
        for (int k = 0; k < 5; ++k)
            if (k < nv) { lsum += acc[k]; lsq += acc[k] * acc[k]; }
    }

    // Deterministic block reduction
#pragma unroll
    for (int o = 16; o > 0; o >>= 1) {
        lsum += __shfl_down_sync(0xffffffffu, lsum, o);
        lsq  += __shfl_down_sync(0xffffffffu, lsq,  o);
    }
    int wid = tid >> 5, lane = tid & 31;
    if (lane == 0) { s_red[wid][0] = lsum; s_red[wid][1] = lsq; }
    __syncthreads();
    if (tid == 0) {
        float a = 0.f, q = 0.f;
#pragma unroll
        for (int w = 0; w < 8; ++w) { a += s_red[w][0]; q += s_red[w][1]; }
        g_part[(b * NBLK + xb) * 2 + 0] = a;
        g_part[(b * NBLK + xb) * 2 + 1] = q;
    }

    img_barrier(tid, b);                       // image b's partials ready

    // ---- Phase C: redundant deterministic stats + normalize + LeakyReLU ----
    const float* __restrict__ part = g_part + b * NBLK * 2;
    float a = 0.f, q = 0.f;
#pragma unroll
    for (int i = 0; i < NBLK; ++i) {
        a += part[i * 2 + 0];
        q += part[i * 2 + 1];
    }
    const float inv_n = 1.0f / (float)NPIX;
    const float mean = a * inv_n;
    const float istd = rsqrtf(q * inv_n - mean * mean + LN_EPS);

    if (act) {
        float* __restrict__ o = out + (size_t)b * NPIX + h * WP + col0;
#pragma unroll
        for (int k = 0; k < 5; ++k) {
            if (k < nv) {
                float v = (acc[k] - mean) * istd;
                o[k] = v >= 0.f ? v : NEG_SLOPE * v;
            }
        }
    }
}

// ---------------------------------------------------------------------------

extern "C" void kernel_launch(void* const* d_in, const int* in_sizes, int n_in,
                              void* d_out, int out_size) {
    const float* x  = (const float*)d_in[0];   // [8,64,256,256]
    const float* cw = (const float*)d_in[1];   // [1,8]
    const float* cb = (const float*)d_in[2];   // [1]
    float* out = (float*)d_out;                // [8,1,257,257]
    (void)in_sizes; (void)n_in; (void)out_size;

    k_all<<<NGRID, NTHR>>>(x, cw, cb, out);
}

// round 11
// speedup vs baseline: 1.1232x; 1.1232x over previous
#include <cuda_runtime.h>

#define BN   8
#define CN   64
#define HN   256
#define WN   256
#define HP   257
#define WP   257
#define HWN  (HN * WN)          // 65536
#define NPIX (HP * WP)          // 66049
#define LN_EPS 1e-5f
#define NEG_SLOPE 0.01f

// Padded channel-sum plane: cs(h,w) stored at [(h+3)*CST + (w+4)].
// 262 rows (cs rows -3..258), stride 268 (cols -4..263). Border is zero
// (zero-initialized device globals; interior-only writes). Composed 6x6
// stencil taps (rows/cols -3..+2) never leave the plane.
#define CROWS 262
#define CST   268
#define CPLANE (CROWS * CST)

#define NBLK  65                // blocks per image
#define NGRID (NBLK * BN)       // 520 blocks, single resident wave
#define NTHR  256
#define Q4    (HWN / 4)         // 16384 float4 columns per image plane

// Scratch (static device globals — allowed)
__device__ float g_csp[BN * CPLANE];       // padded channel sum (~2.25 MB)
__device__ float g_part[BN * NBLK * 2];    // per-block (sum, sumsq)
__device__ unsigned int g_tkt[BN * 32];    // per-image ticket counters, 128B
                                           // apart; monotone (each launch adds
                                           // exactly 2*NBLK per image -> value
                                           // is a multiple of NBLK at launch
                                           // start => graph-replay safe)

// ---------------------------------------------------------------------------
// Per-image ticket barrier: only the 65 blocks of one image synchronize, so
// an image whose chansum finished early proceeds without waiting for the
// global tail. Single resident wave (launch_bounds(256,4), 520 <= 592 cap)
// => spin cannot deadlock.
// ---------------------------------------------------------------------------
__device__ __forceinline__ void img_barrier(int tid, int b) {
    __syncthreads();
    if (tid == 0) {
        __threadfence();                              // publish this block's stores
        unsigned* c = &g_tkt[b * 32];
        unsigned t = atomicAdd(c, 1u) + 1u;
        unsigned target = ((t + NBLK - 1u) / NBLK) * NBLK;
        volatile unsigned* vc = c;
        while (*vc < target) __nanosleep(32);
    }
    __syncthreads();
    __threadfence();                                  // acquire peers' stores
}

// ---------------------------------------------------------------------------
// One persistent kernel: image-local chansum -> per-image barrier -> 36-tap
// composed stencil (+ LN partials) -> per-image barrier -> stats + norm.
// ---------------------------------------------------------------------------
__global__ void __launch_bounds__(NTHR, 4)
k_all(const float* __restrict__ x, const float* __restrict__ cw,
      const float* __restrict__ cb, float* __restrict__ out) {
    __shared__ float s_c6[36];                // composed 6x6 stencil coeffs
    __shared__ float s_tile[10 * CST];        // 10 padded rows (10.5 KB)
    __shared__ float s_red[8][2];

    const int tid = threadIdx.x;
    const int blk = blockIdx.x;
    const int b   = blk / NBLK;               // this block's image
    const int xb  = blk - b * NBLK;           // index within image [0,65)

    // ---- Phase 0: channel sum for image b only (image-local columns) ----
    // Block xb handles columns [xb*Q4/65, (xb+1)*Q4/65): 252-253 columns,
    // one per thread. All producers of image b's plane are in image b's
    // barrier group.
    {
        unsigned base = ((unsigned)xb * Q4) / NBLK;
        unsigned end  = ((unsigned)(xb + 1) * Q4) / NBLK;
        unsigned col  = base + (unsigned)tid;
        if (col < end) {
            const float4* xp = reinterpret_cast<const float4*>(x)
                               + (size_t)b * CN * Q4 + col;
            float ax = 0.f, ay = 0.f, az = 0.f, aw = 0.f;
#pragma unroll
            for (int cc = 0; cc < CN; cc += 8) {
                float4 buf[8];
#pragma unroll
                for (int i = 0; i < 8; ++i)
                    buf[i] = __ldcs(xp + (size_t)(cc + i) * Q4);
#pragma unroll
                for (int i = 0; i < 8; ++i) {
                    ax += buf[i].x; ay += buf[i].y; az += buf[i].z; aw += buf[i].w;
                }
            }
            int p = (int)col * 4;
            int h = p >> 8, w = p & 255;
            *reinterpret_cast<float4*>(
                g_csp + (size_t)b * CPLANE + (h + 3) * CST + (w + 4)) =
                make_float4(ax, ay, az, aw);
        }
    }

    // ---- Composed coefficients: pool(2) o 16-tap shift stencil = 6x6 ----
    if (tid < 36) {
        const signed char tdr[16] = {2,-2, 2,-2, 2,-2, 2,-2, 2,-2, 1,-1, 0,0, -1,1};
        const signed char tdc[16] = {2,-2, 1,-1, 0, 0,-1, 1,-2, 2,-2, 2,-2,2, -2,2};
        const signed char twi[16] = {0, 0, 1, 1, 2, 2, 3, 3, 4, 4, 5, 5, 6,6,  7,7};
        const signed char tsg[16] = {1,-1, 1,-1, 1,-1, 1,-1, 1,-1, 1,-1, 1,-1, 1,-1};
        int r = tid / 6 - 3, c = tid % 6 - 3;
        float acc = 0.f;
        for (int t2 = 0; t2 < 16; ++t2) {
            int ur = r - tdr[t2], uc = c - tdc[t2];
            if ((ur == 0 || ur == -1) && (uc == 0 || uc == -1))
                acc += (float)tsg[t2] * cw[twi[t2]];
        }
        s_c6[tid] = 0.25f * acc;
    }

    img_barrier(tid, b);                      // image b's cs plane ready

    // ---- Phase B: 36-tap stencil from smem tile (R8 layout: 1024-px chunk,
    //      4 strided pixels per thread) ----
    const int p0   = xb * 1024;
    const int pend = (p0 + 1024 < NPIX) ? p0 + 1024 : NPIX;
    const int h0   = p0 / WP;                 // first output row of this chunk
    const float* __restrict__ plane = g_csp + (size_t)b * CPLANE;

    // Tile = padded rows h0..h0+9 (covers taps for output rows h0..h0+4).
    for (int i4 = tid; i4 < 10 * (CST / 4); i4 += NTHR) {
        int r  = i4 / (CST / 4);
        int c4 = i4 - r * (CST / 4);
        int pr = h0 + r;
        float4 v = make_float4(0.f, 0.f, 0.f, 0.f);
        if (pr < CROWS)
            v = *(reinterpret_cast<const float4*>(plane + (size_t)pr * CST) + c4);
        reinterpret_cast<float4*>(s_tile)[r * (CST / 4) + c4] = v;
    }
    __syncthreads();

    const float bias = __ldg(cb);
    float vv[4] = {0.f, 0.f, 0.f, 0.f};
    float lsum = 0.f, lsq = 0.f;
    const int pbase = p0 + tid;
    {
        int  hh[4], jj[4];
        bool ok[4];
#pragma unroll
        for (int k = 0; k < 4; ++k) {
            int p = pbase + k * 256;
            ok[k] = p < pend;
            int h = p / WP;
            hh[k] = h; jj[k] = p - h * WP;
            vv[k] = bias;
        }
        // coeff-outer order: one coeff LDS feeds 4 FMAs
#pragma unroll
        for (int r = 0; r < 6; ++r) {
#pragma unroll
            for (int c = 0; c < 6; ++c) {
                float cf = s_c6[r * 6 + c];
#pragma unroll
                for (int k = 0; k < 4; ++k)
                    if (ok[k])
                        vv[k] = fmaf(cf,
                                     s_tile[(hh[k] - h0 + r) * CST + jj[k] + 1 + c],
                                     vv[k]);
            }
        }
#pragma unroll
        for (int k = 0; k < 4; ++k)
            if (ok[k]) { lsum += vv[k]; lsq += vv[k] * vv[k]; }
    }

    // Deterministic block reduction
#pragma unroll
    for (int o = 16; o > 0; o >>= 1) {
        lsum += __shfl_down_sync(0xffffffffu, lsum, o);
        lsq  += __shfl_down_sync(0xffffffffu, lsq,  o);
    }
    int wid = tid >> 5, lane = tid & 31;
    if (lane == 0) { s_red[wid][0] = lsum; s_red[wid][1] = lsq; }
    __syncthreads();
    if (tid == 0) {
        float a = 0.f, q = 0.f;
#pragma unroll
        for (int w = 0; w < 8; ++w) { a += s_red[w][0]; q += s_red[w][1]; }
        g_part[(b * NBLK + xb) * 2 + 0] = a;
        g_part[(b * NBLK + xb) * 2 + 1] = q;
    }

    img_barrier(tid, b);                      // image b's partials ready

    // ---- Phase C: redundant deterministic stats + normalize + LeakyReLU ----
    const float* __restrict__ part = g_part + b * NBLK * 2;
    float a = 0.f, q = 0.f;
#pragma unroll
    for (int i = 0; i < NBLK; ++i) {
        a += part[i * 2 + 0];
        q += part[i * 2 + 1];
    }
    const float inv_n = 1.0f / (float)NPIX;
    const float mean = a * inv_n;
    const float istd = rsqrtf(q * inv_n - mean * mean + LN_EPS);

    float* __restrict__ o = out + (size_t)b * NPIX;
#pragma unroll
    for (int k = 0; k < 4; ++k) {
        int p = pbase + k * 256;
        if (p < pend) {
            float v = (vv[k] - mean) * istd;
            o[p] = v >= 0.f ? v : NEG_SLOPE * v;
        }
    }
}

// ---------------------------------------------------------------------------

extern "C" void kernel_launch(void* const* d_in, const int* in_sizes, int n_in,
                              void* d_out, int out_size) {
    const float* x  = (const float*)d_in[0];   // [8,64,256,256]
    const float* cw = (const float*)d_in[1];   // [1,8]
    const float* cb = (const float*)d_in[2];   // [1]
    float* out = (float*)d_out;                // [8,1,257,257]
    (void)in_sizes; (void)n_in; (void)out_size;

    k_all<<<NGRID, NTHR>>>(x, cw, cb, out);
}